// round 1
// baseline (speedup 1.0000x reference)
#include <cuda_runtime.h>
#include <math.h>

// ---------------------------------------------------------------------------
// PrettyPCF: pair correlation function, Na=Nb=1536 points, 50 bins.
// Key algorithmic facts exploited:
//  * exp(-16 z^2) < 2e-10 for |z| > 1.2  -> prune pairs with d > (5+1.2)*RMAX
//    (only ~9% of pairs survive) and restrict each pair to a ~26-bin window.
//  * pcf1[b] = GF * sum_{i,j} w[i,b] * exp(...) / (na * area[b] * nb):
//    w can be fused into the pairwise accumulation; GF factored to the end.
// ---------------------------------------------------------------------------

#define NPTS   1536
#define NBINS  50
#define TILE_I 6            // i-points per block; 1536/6 = 256 blocks
#define NTHR   256
#define ZC     1.2f         // Gaussian cutoff in z units

// RMAX = 2*sqrt(1/(2*sqrt(3)*NPOINTS)) — computed in double, constant-folded.
#define RMAX_D (2.0 * sqrt(1.0 / (2.0 * sqrt(3.0) * 1536.0)))

__device__ float g_w[NPTS * NBINS];   // perimeter weights, clipped to [0,4]
__device__ float g_acc[NBINS];        // per-bin accumulator (GF factored out)

// ---------------------------------------------------------------------------
// K1: perimeter weights for disks_a + zero the accumulator
// ---------------------------------------------------------------------------
__global__ void w_kernel(const float* __restrict__ A)
{
    int i = blockIdx.x * blockDim.x + threadIdx.x;
    if (blockIdx.x == 0 && threadIdx.x < NBINS)
        g_acc[threadIdx.x] = 0.0f;
    if (i >= NPTS) return;

    const float TWO_PI = 6.2831853071795864769f;
    const float INV_2PI = 1.0f / TWO_PI;

    float x = A[3 * i];
    float y = A[3 * i + 1];

    // 4 edges: (dx, dy) = (x,y), (1-x,y), (y,x), (1-y,x)
    float ex[4] = { x, 1.0f - x, y, 1.0f - y };
    float ey[4] = { y, y,        x, x        };
    float a1[4], a2[4];
#pragma unroll
    for (int e = 0; e < 4; e++) {
        a1[e] = atan2f(ey[e],        ex[e]);
        a2[e] = atan2f(1.0f - ey[e], ex[e]);
    }

    for (int b = 0; b < NBINS; b++) {
        float rs = (float)((b + 1) * (5.0 / 50.0) * RMAX_D);
        float full = TWO_PI;
#pragma unroll
        for (int e = 0; e < 4; e++) {
            if (rs > ex[e]) {
                float ratio = fminf(ex[e] / rs, 1.0f);
                float alpha = acosf(ratio);
                full -= fminf(alpha, a1[e]) + fminf(alpha, a2[e]);
            }
        }
        float per = fminf(fmaxf(full * INV_2PI, 0.0f), 1.0f);
        float wv  = 1.0f / fmaxf(per, 1e-9f);
        g_w[i * NBINS + b] = fminf(fmaxf(wv, 0.0f), 4.0f);
    }
}

// ---------------------------------------------------------------------------
// K2: pruned pairwise accumulation with fused perimeter weight
// ---------------------------------------------------------------------------
__global__ __launch_bounds__(NTHR)
void pair_kernel(const float* __restrict__ A, const float* __restrict__ B,
                 const int* __restrict__ scp)
{
    __shared__ float sbx[NPTS];
    __shared__ float sby[NPTS];
    __shared__ float sw[TILE_I * NBINS];
    __shared__ float sacc[NBINS];

    const int tid = threadIdx.x;
    const int i0  = blockIdx.x * TILE_I;

    for (int j = tid; j < NPTS; j += NTHR) {
        sbx[j] = B[3 * j];
        sby[j] = B[3 * j + 1];
    }
    for (int t = tid; t < TILE_I * NBINS; t += NTHR) {
        int ii = t / NBINS, b = t % NBINS;
        sw[t] = g_w[(i0 + ii) * NBINS + b];
    }
    if (tid < NBINS) sacc[tid] = 0.0f;
    __syncthreads();

    float ax[TILE_I], ay[TILE_I];
#pragma unroll
    for (int ii = 0; ii < TILE_I; ii++) {
        ax[ii] = A[3 * (i0 + ii)];
        ay[ii] = A[3 * (i0 + ii) + 1];
    }

    const int   same  = *scp;
    const float invR  = (float)(1.0 / RMAX_D);
    // contributes if exists b: |RS[b] - d| < ZC*RMAX ; RS max = 5*RMAX
    const float dmax  = (float)((5.0 + (double)ZC) * RMAX_D);
    const float cut2  = dmax * dmax;

    for (int j = tid; j < NPTS; j += NTHR) {
        float bx = sbx[j], by = sby[j];
#pragma unroll
        for (int ii = 0; ii < TILE_I; ii++) {
            float dx = ax[ii] - bx;
            float dy = ay[ii] - by;
            float d2 = fmaf(dx, dx, dy * dy);
            if (d2 < cut2) {
                if (same && (i0 + ii) == j) continue;
                float d = sqrtf(d2);
                float u = d * invR;                 // d / RMAX
                // bin b contributes if |0.1*(b+1) - u| <= ZC
                // -> b+1 in [10*(u-ZC), 10*(u+ZC)]; widen by 1 for safety.
                int b0 = (int)(10.0f * (u - ZC)) - 1;
                if (b0 < 0) b0 = 0;
                int b1 = (int)(10.0f * (u + ZC));
                if (b1 > NBINS - 1) b1 = NBINS - 1;
                float z = 0.1f * (float)(b0 + 1) - u;
                const float* wrow = &sw[ii * NBINS];
                for (int b = b0; b <= b1; b++) {
                    float e = __expf(-16.0f * z * z);
                    atomicAdd(&sacc[b], e * wrow[b]);
                    z += 0.1f;
                }
            }
        }
    }
    __syncthreads();
    if (tid < NBINS) atomicAdd(&g_acc[tid], sacc[tid]);
}

// ---------------------------------------------------------------------------
// K3: finalize -> out[b*2] = RS[b]/RMAX, out[b*2+1] = pcf1[b]
// ---------------------------------------------------------------------------
__global__ void fin_kernel(float* __restrict__ out)
{
    int b = threadIdx.x;
    if (b >= NBINS) return;
    double rs_d   = (b + 1) * (5.0 / 50.0) * RMAX_D;
    double inner  = fmax(0.0, rs_d - 0.5 * RMAX_D);
    double outer  = rs_d + 0.5 * RMAX_D;
    float  area   = (float)(M_PI * (outer * outer - inner * inner));
    const float GF = (float)(1.0 / (sqrt(M_PI) * 0.25));

    float s   = g_acc[b] * GF;
    float pcf = s / 1536.0f / (area * 1536.0f);

    out[2 * b]     = (float)rs_d / (float)RMAX_D;
    out[2 * b + 1] = pcf;
}

// ---------------------------------------------------------------------------
extern "C" void kernel_launch(void* const* d_in, const int* in_sizes, int n_in,
                              void* d_out, int out_size)
{
    const float* A  = (const float*)d_in[0];   // disks_a [1536,3]
    const float* B  = (const float*)d_in[1];   // disks_b [1536,3]
    const int*   sc = (const int*)d_in[2];     // same_category scalar
    float* out = (float*)d_out;

    w_kernel<<<(NPTS + 127) / 128, 128>>>(A);
    pair_kernel<<<NPTS / TILE_I, NTHR>>>(A, B, sc);
    fin_kernel<<<1, 64>>>(out);
}

// round 2
// speedup vs baseline: 5.9044x; 5.9044x over previous
#include <cuda_runtime.h>
#include <math.h>

// ---------------------------------------------------------------------------
// PrettyPCF: pair correlation, Na=Nb=1536, 50 bins.
// R2 design:
//  * w_kernel: one thread per (point, bin)  -> 76800 threads (was 1536).
//  * pair_kernel: phase A finds surviving pairs (d < 6.2*RMAX, ~9%) into a
//    shared queue; phase B warps consume entries with lane==bin, accumulating
//    into per-lane REGISTERS (bins l and l+32). No per-bin atomics in the
//    hot path. All 50 bins computed per survivor (matches reference, which
//    has no bin cutoff; exp underflows to 0 outside the window anyway).
// ---------------------------------------------------------------------------

#define NPTS   1536
#define NBINS  50
#define TILE_I 6            // i-points per block; 1536/6 = 256 blocks
#define NTHR   256
#define NWARP  (NTHR / 32)
#define NCHUNK (NPTS / NTHR)    // 6
#define QCAP   (NTHR * TILE_I)  // worst-case survivors per chunk = 1536
#define ZC     1.2f

#define RMAX_D (2.0 * sqrt(1.0 / (2.0 * sqrt(3.0) * 1536.0)))

__device__ float g_w[NPTS * NBINS];   // perimeter weights, clipped to [0,4]
__device__ float g_acc[NBINS];        // per-bin accumulator (GF factored out)

// ---------------------------------------------------------------------------
// K1: perimeter weights, one thread per (i, b). Also zeroes g_acc.
// ---------------------------------------------------------------------------
__global__ __launch_bounds__(256)
void w_kernel(const float* __restrict__ A)
{
    int t = blockIdx.x * 256 + threadIdx.x;
    if (blockIdx.x == 0 && threadIdx.x < NBINS)
        g_acc[threadIdx.x] = 0.0f;
    if (t >= NPTS * NBINS) return;

    int i = t / NBINS;
    int b = t - i * NBINS;

    float x = A[3 * i];
    float y = A[3 * i + 1];
    float rs = (float)((b + 1) * (5.0 / 50.0) * RMAX_D);

    const float TWO_PI = 6.2831853071795864769f;
    float full = TWO_PI;

    float ex[4] = { x, 1.0f - x, y, 1.0f - y };
    float ey[4] = { y, y,        x, x        };
#pragma unroll
    for (int e = 0; e < 4; e++) {
        if (rs > ex[e]) {
            float ratio = fminf(ex[e] / rs, 1.0f);   // ex>=0 so lower clip moot
            float alpha = acosf(ratio);
            float a1 = atan2f(ey[e],        ex[e]);
            float a2 = atan2f(1.0f - ey[e], ex[e]);
            full -= fminf(alpha, a1) + fminf(alpha, a2);
        }
    }
    float per = fminf(fmaxf(full * (1.0f / TWO_PI), 0.0f), 1.0f);
    float wv  = 1.0f / fmaxf(per, 1e-9f);
    g_w[t] = fminf(wv, 4.0f);   // w >= 1 always, so only upper clip needed
}

// ---------------------------------------------------------------------------
// K2: survivor-queue pairwise accumulation, lanes-over-bins
// ---------------------------------------------------------------------------
__global__ __launch_bounds__(NTHR)
void pair_kernel(const float* __restrict__ A, const float* __restrict__ B,
                 const int* __restrict__ scp)
{
    __shared__ float sbx[NPTS];
    __shared__ float sby[NPTS];
    __shared__ float sw[TILE_I * NBINS];
    __shared__ float qu[QCAP];
    __shared__ int   qi[QCAP];
    __shared__ float sacc[NBINS];
    __shared__ int   qcount;

    const int tid  = threadIdx.x;
    const int lane = tid & 31;
    const int wid  = tid >> 5;
    const int i0   = blockIdx.x * TILE_I;

    for (int j = tid; j < NPTS; j += NTHR) {
        sbx[j] = B[3 * j];
        sby[j] = B[3 * j + 1];
    }
    for (int t = tid; t < TILE_I * NBINS; t += NTHR)
        sw[t] = g_w[i0 * NBINS + t];
    if (tid < NBINS) sacc[tid] = 0.0f;

    float ax[TILE_I], ay[TILE_I];
#pragma unroll
    for (int ii = 0; ii < TILE_I; ii++) {
        ax[ii] = A[3 * (i0 + ii)];
        ay[ii] = A[3 * (i0 + ii) + 1];
    }

    const int   same = *scp;
    const float invR = (float)(1.0 / RMAX_D);
    const float dmax = (float)((5.0 + (double)ZC) * RMAX_D);
    const float cut2 = dmax * dmax;

    // Per-lane register accumulators: lane l owns bins l and l+32.
    float acc1 = 0.0f, acc2 = 0.0f;
    const float z1base = 0.1f * (float)(lane + 1);   // RS[l]/RMAX

    for (int chunk = 0; chunk < NCHUNK; chunk++) {
        if (tid == 0) qcount = 0;
        __syncthreads();

        // ---- Phase A: distance test, push survivors ----
        int   j  = chunk * NTHR + tid;
        float bx = sbx[j], by = sby[j];
#pragma unroll
        for (int ii = 0; ii < TILE_I; ii++) {
            float dx = ax[ii] - bx;
            float dy = ay[ii] - by;
            float d2 = fmaf(dx, dx, dy * dy);
            if (d2 < cut2 && !(same && (i0 + ii) == j)) {
                int slot = atomicAdd(&qcount, 1);
                qu[slot] = sqrtf(d2) * invR;    // u = d / RMAX
                qi[slot] = ii;
            }
        }
        __syncthreads();

        // ---- Phase B: warps drain queue, lane == bin ----
        int nq = qcount;
        for (int e = wid; e < nq; e += NWARP) {
            float u  = qu[e];                    // LDS broadcast
            int   ii = qi[e];
            const float* wrow = &sw[ii * NBINS];
            float z1 = z1base - u;
            acc1 += __expf(-16.0f * z1 * z1) * wrow[lane];
            if (lane < NBINS - 32) {
                float z2 = z1 + 3.2f;
                acc2 += __expf(-16.0f * z2 * z2) * wrow[lane + 32];
            }
        }
        __syncthreads();   // protect qcount/qu reuse next chunk
    }

    // ---- Block reduction: 8 warps x 50 bins via shared atomics ----
    atomicAdd(&sacc[lane], acc1);
    if (lane < NBINS - 32) atomicAdd(&sacc[lane + 32], acc2);
    __syncthreads();
    if (tid < NBINS) atomicAdd(&g_acc[tid], sacc[tid]);
}

// ---------------------------------------------------------------------------
// K3: finalize -> out[b*2] = RS[b]/RMAX, out[b*2+1] = pcf1[b]
// ---------------------------------------------------------------------------
__global__ void fin_kernel(float* __restrict__ out)
{
    int b = threadIdx.x;
    if (b >= NBINS) return;
    double rs_d  = (b + 1) * (5.0 / 50.0) * RMAX_D;
    double inner = fmax(0.0, rs_d - 0.5 * RMAX_D);
    double outer = rs_d + 0.5 * RMAX_D;
    float  area  = (float)(M_PI * (outer * outer - inner * inner));
    const float GF = (float)(1.0 / (sqrt(M_PI) * 0.25));

    float s   = g_acc[b] * GF;
    float pcf = s / 1536.0f / (area * 1536.0f);

    out[2 * b]     = (float)rs_d / (float)RMAX_D;
    out[2 * b + 1] = pcf;
}

// ---------------------------------------------------------------------------
extern "C" void kernel_launch(void* const* d_in, const int* in_sizes, int n_in,
                              void* d_out, int out_size)
{
    const float* A  = (const float*)d_in[0];   // disks_a [1536,3]
    const float* B  = (const float*)d_in[1];   // disks_b [1536,3]
    const int*   sc = (const int*)d_in[2];     // same_category scalar
    float* out = (float*)d_out;

    w_kernel<<<(NPTS * NBINS + 255) / 256, 256>>>(A);
    pair_kernel<<<NPTS / TILE_I, NTHR>>>(A, B, sc);
    fin_kernel<<<1, 64>>>(out);
}